// round 2
// baseline (speedup 1.0000x reference)
#include <cuda_runtime.h>
#include <cstdint>
#include <math.h>

typedef unsigned long long ull;

__device__ __forceinline__ ull pack2(float lo, float hi) {
    ull r; asm("mov.b64 %0, {%1, %2};" : "=l"(r) : "f"(lo), "f"(hi)); return r;
}
__device__ __forceinline__ void unpack2(ull v, float& lo, float& hi) {
    asm("mov.b64 {%0, %1}, %2;" : "=f"(lo), "=f"(hi) : "l"(v));
}
__device__ __forceinline__ ull ffma2(ull a, ull b, ull c) {
    ull d; asm("fma.rn.f32x2 %0, %1, %2, %3;" : "=l"(d) : "l"(a), "l"(b), "l"(c)); return d;
}

static constexpr int B = 8, C = 128, T = 128, F = 512, K = 64;
static constexpr int FC = 128;     // F columns per CTA in main kernel
static constexpr int PXF = 128;    // pitch (floats) for 128-wide smem tiles
static constexpr int PXK = 64;     // pitch (floats) for 64-wide smem tiles

// scratch for k/v projections of the latent path: [b*T+t][c][k]
__device__ float g_kbuf[(size_t)B * T * C * K];
__device__ float g_vbuf[(size_t)B * T * C * K];

__device__ __forceinline__ float silu_f(float g) {
    // g * sigmoid(g); fast exp + fast div (g/-inf handled: rcp(inf)=0)
    float e = __expf(-g);
    return __fdividef(g, 1.0f + e);
}

// ---------------------------------------------------------------------------
// Core SIMT GEMM: out[r][f] = sum_c W[r][c] * Xin[c][f], 256 threads.
// r = ty + 16*i (i < RT), f = 2*(tx + 16*jp) + {0,1} (jp < NP).
// Weights staged as DUPLICATED (w,w) f32x2 pairs in smem Wts, pitch CH+1 ull,
// with register prefetch of the next chunk so LDG latency is off the
// critical path. Inner loop is pure LDS.64 + FFMA2.
// ---------------------------------------------------------------------------
template <int RT, int NP, int PX, int CH>
__device__ __forceinline__ void gemm_core(
    const float* __restrict__ Wglob,   // [RT*16][128] row-major
    const float* __restrict__ Xin,     // smem tile, pitch PX
    ull* __restrict__ Wts,             // smem staging, (RT*16) x (CH+1) ull
    ull acc[RT][NP], int tid)
{
    const int tx = tid & 15, ty = tid >> 4;
    constexpr int R  = RT * 16;
    constexpr int PW = CH + 1;
    constexpr int C4 = CH / 4;                 // float4 per row per chunk
    constexpr int PT = (R * C4) / 256;         // float4 per thread per chunk
    static_assert((R * C4) % 256 == 0, "staging divisibility");

    float4 pf[PT];
    #pragma unroll
    for (int p = 0; p < PT; ++p) {
        int idx = tid + p * 256;
        int r = idx / C4, q = idx % C4;
        pf[p] = *reinterpret_cast<const float4*>(Wglob + r * 128 + q * 4);
    }

    for (int c0 = 0; c0 < 128; c0 += CH) {
        __syncthreads();   // prior readers of Wts are done
        #pragma unroll
        for (int p = 0; p < PT; ++p) {
            int idx = tid + p * 256;
            int r = idx / C4, q = idx % C4;
            ull* d = Wts + r * PW + q * 4;
            d[0] = pack2(pf[p].x, pf[p].x);
            d[1] = pack2(pf[p].y, pf[p].y);
            d[2] = pack2(pf[p].z, pf[p].z);
            d[3] = pack2(pf[p].w, pf[p].w);
        }
        __syncthreads();
        if (c0 + CH < 128) {   // prefetch next chunk while computing this one
            #pragma unroll
            for (int p = 0; p < PT; ++p) {
                int idx = tid + p * 256;
                int r = idx / C4, q = idx % C4;
                pf[p] = *reinterpret_cast<const float4*>(Wglob + r * 128 + c0 + CH + q * 4);
            }
        }
        #pragma unroll 4
        for (int cc = 0; cc < CH; ++cc) {
            const float* xrow = Xin + (c0 + cc) * PX;
            ull xp[NP];
            #pragma unroll
            for (int jp = 0; jp < NP; ++jp)
                xp[jp] = *reinterpret_cast<const ull*>(xrow + 2 * (tx + 16 * jp));
            #pragma unroll
            for (int i = 0; i < RT; ++i) {
                ull wp = Wts[(ty + 16 * i) * PW + cc];
                #pragma unroll
                for (int jp = 0; jp < NP; ++jp)
                    acc[i][jp] = ffma2(wp, xp[jp], acc[i][jp]);
            }
        }
    }
}

// ---------------------------------------------------------------------------
// Kernel 1: latent path. One CTA per (b,t) frame.
// ---------------------------------------------------------------------------
static constexpr int K1_XL = 0;
static constexpr int K1_LH = 128 * PXK;                 // 8192
static constexpr int K1_WT = K1_LH + 128 * PXK;         // 16384 (floats)
static constexpr int K1_WT_ULL = 128 * 17;              // 2176 ull
static constexpr int K1_RS = K1_WT + 2 * K1_WT_ULL;     // floats
static constexpr int K1_SMEM_BYTES = (K1_RS + 64) * 4;

__global__ void __launch_bounds__(256, 2) latent_kernel(
    const float* __restrict__ latent, const float* __restrict__ lp_gamma,
    const float* __restrict__ lp_w,   const float* __restrict__ lp_b,
    const float* __restrict__ k_w,    const float* __restrict__ k_b,
    const float* __restrict__ v_w,    const float* __restrict__ v_b)
{
    extern __shared__ float sm[];
    float* Xl  = sm + K1_XL;
    float* Lh  = sm + K1_LH;
    ull*   Wts = reinterpret_cast<ull*>(sm + K1_WT);
    float* rstd = sm + K1_RS;
    const int tid = threadIdx.x;
    const int frame = blockIdx.x;            // b*T + t
    const int b = frame / T, t = frame % T;
    const int tx = tid & 15, ty = tid >> 4;

    // load latent frame [128][64] (rows strided T*K in global)
    const float* src = latent + ((size_t)b * C * T + t) * K;
    #pragma unroll
    for (int idx = tid; idx < 128 * 16; idx += 256) {
        int r = idx >> 4, q = idx & 15;
        float4 v = *reinterpret_cast<const float4*>(src + (size_t)r * (T * K) + q * 4);
        *reinterpret_cast<float4*>(Xl + r * PXK + q * 4) = v;
    }
    __syncthreads();
    if (tid < 64) {
        float s0 = 0, s1 = 0, s2 = 0, s3 = 0;
        for (int c = 0; c < 128; c += 4) {
            float a = Xl[c * PXK + tid], bb = Xl[(c + 1) * PXK + tid];
            float cc = Xl[(c + 2) * PXK + tid], dd = Xl[(c + 3) * PXK + tid];
            s0 += a * a; s1 += bb * bb; s2 += cc * cc; s3 += dd * dd;
        }
        rstd[tid] = rsqrtf((s0 + s1 + s2 + s3) * (1.0f / 128.0f) + 1e-6f);
    }
    __syncthreads();
    #pragma unroll
    for (int idx = tid; idx < 128 * 16; idx += 256) {
        int r = idx >> 4, q = idx & 15;
        float g = lp_gamma[r];
        float* d = Xl + r * PXK + q * 4;
        d[0] *= rstd[q * 4 + 0] * g; d[1] *= rstd[q * 4 + 1] * g;
        d[2] *= rstd[q * 4 + 2] * g; d[3] *= rstd[q * 4 + 3] * g;
    }
    // (gemm_core begins with __syncthreads)

    // latent_h = silu(lp_w @ Xn + lp_b)
    {
        ull acc[8][2] = {};
        gemm_core<8, 2, PXK, 16>(lp_w, Xl, Wts, acc, tid);
        #pragma unroll
        for (int i = 0; i < 8; ++i) {
            int r = ty + 16 * i;
            float bias = lp_b[r];
            #pragma unroll
            for (int jp = 0; jp < 2; ++jp) {
                float lo, hi; unpack2(acc[i][jp], lo, hi);
                int fl = 2 * (tx + 16 * jp);
                Lh[r * PXK + fl]     = silu_f(lo + bias);
                Lh[r * PXK + fl + 1] = silu_f(hi + bias);
            }
        }
    }
    // k projection -> g_kbuf
    {
        ull acc[8][2] = {};
        gemm_core<8, 2, PXK, 16>(k_w, Lh, Wts, acc, tid);
        float* dst = g_kbuf + (size_t)frame * (C * K);
        #pragma unroll
        for (int i = 0; i < 8; ++i) {
            int r = ty + 16 * i;
            float bias = k_b[r];
            #pragma unroll
            for (int jp = 0; jp < 2; ++jp) {
                float lo, hi; unpack2(acc[i][jp], lo, hi);
                int fl = 2 * (tx + 16 * jp);
                *reinterpret_cast<float2*>(dst + r * K + fl) = make_float2(lo + bias, hi + bias);
            }
        }
    }
    // v projection -> g_vbuf
    {
        ull acc[8][2] = {};
        gemm_core<8, 2, PXK, 16>(v_w, Lh, Wts, acc, tid);
        float* dst = g_vbuf + (size_t)frame * (C * K);
        #pragma unroll
        for (int i = 0; i < 8; ++i) {
            int r = ty + 16 * i;
            float bias = v_b[r];
            #pragma unroll
            for (int jp = 0; jp < 2; ++jp) {
                float lo, hi; unpack2(acc[i][jp], lo, hi);
                int fl = 2 * (tx + 16 * jp);
                *reinterpret_cast<float2*>(dst + r * K + fl) = make_float2(lo + bias, hi + bias);
            }
        }
    }
}

// ---------------------------------------------------------------------------
// Kernel 2: fused side path + attention + FFN. One CTA per (b, t, f-chunk).
// ---------------------------------------------------------------------------
static constexpr int K2_XS = 0;
static constexpr int K2_HS = 128 * PXF;                 // 16384
static constexpr int K2_KS = K2_HS + 128 * PXF;         // 32768
static constexpr int K2_VS = K2_KS + 128 * PXK;         // 40960
static constexpr int K2_WT = K2_VS + 128 * PXK;         // 49152 (floats)
static constexpr int K2_WT_ULL = 256 * 9;               // 2304 ull (worst case)
static constexpr int K2_RS = K2_WT + 2 * K2_WT_ULL;     // 53760
static constexpr int K2_SMEM_BYTES = (K2_RS + 128) * 4; // 215,552 B

__global__ void __launch_bounds__(256, 1) main_kernel(
    const float* __restrict__ side,      const float* __restrict__ basis,
    const float* __restrict__ qn_gamma,
    const float* __restrict__ qmlp_in_w, const float* __restrict__ qmlp_in_b,
    const float* __restrict__ qmlp_out_w,const float* __restrict__ qmlp_out_b,
    const float* __restrict__ q_w,       const float* __restrict__ q_b,
    const float* __restrict__ o_w,       const float* __restrict__ o_b,
    const float* __restrict__ ffn_gamma,
    const float* __restrict__ ffn_in_w,  const float* __restrict__ ffn_in_b,
    const float* __restrict__ ffn_out_w, const float* __restrict__ ffn_out_b,
    const float* __restrict__ score_scale, const float* __restrict__ prior_scale,
    const float* __restrict__ query_skip_scale,
    float* __restrict__ out)
{
    extern __shared__ float sm[];
    float* Xs  = sm + K2_XS;
    float* Hs  = sm + K2_HS;
    float* Ks  = sm + K2_KS;
    float* Vs  = sm + K2_VS;
    ull*   Wts = reinterpret_cast<ull*>(sm + K2_WT);
    float* rstd = sm + K2_RS;

    const int tid = threadIdx.x;
    const int fc = blockIdx.x;      // 0..3
    const int t  = blockIdx.y;
    const int b  = blockIdx.z;
    const int f0 = fc * FC;
    const int tx = tid & 15, ty = tid >> 4;
    const int frame = b * T + t;

    // ---- load k/v frame into smem (linear copy, pitch == K) ----
    {
        const float4* ksrc = reinterpret_cast<const float4*>(g_kbuf + (size_t)frame * (C * K));
        const float4* vsrc = reinterpret_cast<const float4*>(g_vbuf + (size_t)frame * (C * K));
        float4* kdst = reinterpret_cast<float4*>(Ks);
        float4* vdst = reinterpret_cast<float4*>(Vs);
        #pragma unroll
        for (int idx = tid; idx < 128 * 16; idx += 256) {
            kdst[idx] = ksrc[idx];
            vdst[idx] = vsrc[idx];
        }
    }
    // ---- load side chunk [128][128] ----
    const float* sbase = side + ((size_t)b * C * T + t) * F + f0;
    #pragma unroll
    for (int idx = tid; idx < 128 * 32; idx += 256) {
        int r = idx >> 5, q = idx & 31;
        float4 v = *reinterpret_cast<const float4*>(sbase + (size_t)r * (T * F) + q * 4);
        *reinterpret_cast<float4*>(Xs + r * PXF + q * 4) = v;
    }
    __syncthreads();
    // ---- rmsnorm (axis C) ----
    if (tid < 128) {
        float s0 = 0, s1 = 0, s2 = 0, s3 = 0;
        for (int c = 0; c < 128; c += 4) {
            float a = Xs[c * PXF + tid], bb = Xs[(c + 1) * PXF + tid];
            float cc = Xs[(c + 2) * PXF + tid], dd = Xs[(c + 3) * PXF + tid];
            s0 += a * a; s1 += bb * bb; s2 += cc * cc; s3 += dd * dd;
        }
        rstd[tid] = rsqrtf((s0 + s1 + s2 + s3) * (1.0f / 128.0f) + 1e-6f);
    }
    __syncthreads();
    #pragma unroll
    for (int idx = tid; idx < 128 * 32; idx += 256) {
        int r = idx >> 5, q = idx & 31;
        float g = qn_gamma[r];
        float* d = Xs + r * PXF + q * 4;
        d[0] *= rstd[q * 4 + 0] * g; d[1] *= rstd[q * 4 + 1] * g;
        d[2] *= rstd[q * 4 + 2] * g; d[3] *= rstd[q * 4 + 3] * g;
    }

    // ---- GEMM1: qmlp_in (256 rows, chunk 8), gated -> m in Hs ----
    {
        ull acc[16][4] = {};
        gemm_core<16, 4, PXF, 8>(qmlp_in_w, Xs, Wts, acc, tid);
        #pragma unroll
        for (int i = 0; i < 8; ++i) {
            int r = ty + 16 * i;
            float ba = qmlp_in_b[r], bg = qmlp_in_b[r + 128];
            #pragma unroll
            for (int jp = 0; jp < 4; ++jp) {
                float a0, a1, g0, g1;
                unpack2(acc[i][jp], a0, a1);
                unpack2(acc[i + 8][jp], g0, g1);
                int fl = 2 * (tx + 16 * jp);
                Hs[r * PXF + fl]     = (a0 + ba) * silu_f(g0 + bg);
                Hs[r * PXF + fl + 1] = (a1 + ba) * silu_f(g1 + bg);
            }
        }
    }
    // ---- GEMM2: qmlp_out -> query_h in Xs ----
    {
        ull acc[8][4] = {};
        gemm_core<8, 4, PXF, 16>(qmlp_out_w, Hs, Wts, acc, tid);
        #pragma unroll
        for (int i = 0; i < 8; ++i) {
            int r = ty + 16 * i;
            float bias = qmlp_out_b[r];
            #pragma unroll
            for (int jp = 0; jp < 4; ++jp) {
                float lo, hi; unpack2(acc[i][jp], lo, hi);
                int fl = 2 * (tx + 16 * jp);
                Xs[r * PXF + fl] = lo + bias; Xs[r * PXF + fl + 1] = hi + bias;
            }
        }
    }
    // ---- GEMM3: q projection -> Hs ----
    {
        ull acc[8][4] = {};
        gemm_core<8, 4, PXF, 16>(q_w, Xs, Wts, acc, tid);
        #pragma unroll
        for (int i = 0; i < 8; ++i) {
            int r = ty + 16 * i;
            float bias = q_b[r];
            #pragma unroll
            for (int jp = 0; jp < 4; ++jp) {
                float lo, hi; unpack2(acc[i][jp], lo, hi);
                int fl = 2 * (tx + 16 * jp);
                Hs[r * PXF + fl] = lo + bias; Hs[r * PXF + fl + 1] = hi + bias;
            }
        }
    }
    __syncthreads();   // q fully in Hs before scores

    // ---- scores [f][k] + softmax over k ----
    const int kg = tid & 7, fg = tid >> 3;    // k-octet lives in lane bits 0..2
    float wgt[4][8];
    {
        ull sacc[4][4] = {};
        #pragma unroll 4
        for (int c = 0; c < 128; ++c) {
            const float* qrow = Hs + c * PXF + fg * 4;
            const float* krow = Ks + c * PXK + kg * 8;
            ull kp[4];
            #pragma unroll
            for (int jp = 0; jp < 4; ++jp)
                kp[jp] = *reinterpret_cast<const ull*>(krow + 2 * jp);
            #pragma unroll
            for (int i = 0; i < 4; ++i) {
                float qv = qrow[i];
                ull qp = pack2(qv, qv);
                #pragma unroll
                for (int jp = 0; jp < 4; ++jp)
                    sacc[i][jp] = ffma2(qp, kp[jp], sacc[i][jp]);
            }
        }
        const float ssc = *score_scale, psc = *prior_scale;
        #pragma unroll
        for (int i = 0; i < 4; ++i) {
            float s[8];
            #pragma unroll
            for (int jp = 0; jp < 4; ++jp) unpack2(sacc[i][jp], s[2 * jp], s[2 * jp + 1]);
            int fglob = f0 + fg * 4 + i;
            #pragma unroll
            for (int j = 0; j < 8; ++j)
                s[j] = s[j] * ssc + basis[(kg * 8 + j) * F + fglob] * psc;
            float m = s[0];
            #pragma unroll
            for (int j = 1; j < 8; ++j) m = fmaxf(m, s[j]);
            #pragma unroll
            for (int d = 1; d < 8; d <<= 1) m = fmaxf(m, __shfl_xor_sync(0xffffffffu, m, d));
            float sum = 0;
            #pragma unroll
            for (int j = 0; j < 8; ++j) { float e = __expf(s[j] - m); wgt[i][j] = e; sum += e; }
            #pragma unroll
            for (int d = 1; d < 8; d <<= 1) sum += __shfl_xor_sync(0xffffffffu, sum, d);
            float inv = __frcp_rn(sum);
            #pragma unroll
            for (int j = 0; j < 8; ++j) wgt[i][j] *= inv;
        }
    }
    __syncthreads();   // all reads of Ks done
    {   // store weights transposed into the dead Ks region: Ws[k][f], pitch PXF
        float* Ws = Ks;
        #pragma unroll
        for (int i = 0; i < 4; ++i) {
            int fl = fg * 4 + i;
            #pragma unroll
            for (int j = 0; j < 8; ++j) Ws[(kg * 8 + j) * PXF + fl] = wgt[i][j];
        }
    }
    __syncthreads();
    // ---- attended[c][f] = sum_k Ws[k][f] * Vs[c][k] -> Hs ----
    {
        ull acc[8][4] = {};
        const float* Ws = Ks;
        #pragma unroll 4
        for (int kk = 0; kk < 64; ++kk) {
            ull xp[4];
            #pragma unroll
            for (int jp = 0; jp < 4; ++jp)
                xp[jp] = *reinterpret_cast<const ull*>(Ws + kk * PXF + 2 * (tx + 16 * jp));
            #pragma unroll
            for (int i = 0; i < 8; ++i) {
                float v = Vs[(ty + 16 * i) * PXK + kk];
                ull vp = pack2(v, v);
                #pragma unroll
                for (int jp = 0; jp < 4; ++jp)
                    acc[i][jp] = ffma2(vp, xp[jp], acc[i][jp]);
            }
        }
        #pragma unroll
        for (int i = 0; i < 8; ++i) {
            int r = ty + 16 * i;
            #pragma unroll
            for (int jp = 0; jp < 4; ++jp) {
                float lo, hi; unpack2(acc[i][jp], lo, hi);
                int fl = 2 * (tx + 16 * jp);
                Hs[r * PXF + fl] = lo; Hs[r * PXF + fl + 1] = hi;
            }
        }
    }
    // ---- GEMM4: hidden = o_w @ attended + o_b + qss*query_h  -> Xs (in place) ----
    {
        ull acc[8][4] = {};
        gemm_core<8, 4, PXF, 16>(o_w, Hs, Wts, acc, tid);
        const float qs = *query_skip_scale;
        #pragma unroll
        for (int i = 0; i < 8; ++i) {
            int r = ty + 16 * i;
            float bias = o_b[r];
            #pragma unroll
            for (int jp = 0; jp < 4; ++jp) {
                float lo, hi; unpack2(acc[i][jp], lo, hi);
                int fl = 2 * (tx + 16 * jp);
                lo += bias + qs * Xs[r * PXF + fl];
                hi += bias + qs * Xs[r * PXF + fl + 1];
                Xs[r * PXF + fl] = lo; Xs[r * PXF + fl + 1] = hi;
            }
        }
    }
    __syncthreads();
    // ---- FFN rmsnorm: Hs = rmsnorm(Xs)*ffn_gamma ----
    if (tid < 128) {
        float s0 = 0, s1 = 0, s2 = 0, s3 = 0;
        for (int c = 0; c < 128; c += 4) {
            float a = Xs[c * PXF + tid], bb = Xs[(c + 1) * PXF + tid];
            float cc = Xs[(c + 2) * PXF + tid], dd = Xs[(c + 3) * PXF + tid];
            s0 += a * a; s1 += bb * bb; s2 += cc * cc; s3 += dd * dd;
        }
        rstd[tid] = rsqrtf((s0 + s1 + s2 + s3) * (1.0f / 128.0f) + 1e-6f);
    }
    __syncthreads();
    #pragma unroll
    for (int idx = tid; idx < 128 * 32; idx += 256) {
        int r = idx >> 5, q = idx & 31;
        float g = ffn_gamma[r];
        const float* s = Xs + r * PXF + q * 4;
        float* d = Hs + r * PXF + q * 4;
        d[0] = s[0] * rstd[q * 4 + 0] * g; d[1] = s[1] * rstd[q * 4 + 1] * g;
        d[2] = s[2] * rstd[q * 4 + 2] * g; d[3] = s[3] * rstd[q * 4 + 3] * g;
    }
    // ---- GEMM5: ffn_in (256 rows, chunk 8), gated -> m2 back into Hs ----
    {
        ull acc[16][4] = {};
        gemm_core<16, 4, PXF, 8>(ffn_in_w, Hs, Wts, acc, tid);
        __syncthreads();   // everyone done READING Hs before we overwrite it
        #pragma unroll
        for (int i = 0; i < 8; ++i) {
            int r = ty + 16 * i;
            float ba = ffn_in_b[r], bg = ffn_in_b[r + 128];
            #pragma unroll
            for (int jp = 0; jp < 4; ++jp) {
                float a0, a1, g0, g1;
                unpack2(acc[i][jp], a0, a1);
                unpack2(acc[i + 8][jp], g0, g1);
                int fl = 2 * (tx + 16 * jp);
                Hs[r * PXF + fl]     = (a0 + ba) * silu_f(g0 + bg);
                Hs[r * PXF + fl + 1] = (a1 + ba) * silu_f(g1 + bg);
            }
        }
    }
    // ---- GEMM6: out = ffn_out @ m2 + ffn_out_b + hidden -> global ----
    {
        ull acc[8][4] = {};
        gemm_core<8, 4, PXF, 16>(ffn_out_w, Hs, Wts, acc, tid);
        float* obase = out + ((size_t)b * C * T + t) * F + f0;
        #pragma unroll
        for (int i = 0; i < 8; ++i) {
            int r = ty + 16 * i;
            float bias = ffn_out_b[r];
            #pragma unroll
            for (int jp = 0; jp < 4; ++jp) {
                float lo, hi; unpack2(acc[i][jp], lo, hi);
                int fl = 2 * (tx + 16 * jp);
                lo += bias + Xs[r * PXF + fl];
                hi += bias + Xs[r * PXF + fl + 1];
                *reinterpret_cast<float2*>(obase + (size_t)r * (T * F) + fl) = make_float2(lo, hi);
            }
        }
    }
}

// ---------------------------------------------------------------------------
extern "C" void kernel_launch(void* const* d_in, const int* in_sizes, int n_in,
                              void* d_out, int out_size)
{
    const float* latent      = (const float*)d_in[0];
    const float* side        = (const float*)d_in[1];
    const float* basis       = (const float*)d_in[2];
    const float* lp_gamma    = (const float*)d_in[3];
    const float* lp_w        = (const float*)d_in[4];
    const float* lp_b        = (const float*)d_in[5];
    const float* qn_gamma    = (const float*)d_in[6];
    const float* qmlp_in_w   = (const float*)d_in[7];
    const float* qmlp_in_b   = (const float*)d_in[8];
    const float* qmlp_out_w  = (const float*)d_in[9];
    const float* qmlp_out_b  = (const float*)d_in[10];
    const float* q_w         = (const float*)d_in[11];
    const float* q_b         = (const float*)d_in[12];
    const float* k_w         = (const float*)d_in[13];
    const float* k_b         = (const float*)d_in[14];
    const float* v_w         = (const float*)d_in[15];
    const float* v_b         = (const float*)d_in[16];
    const float* o_w         = (const float*)d_in[17];
    const float* o_b         = (const float*)d_in[18];
    const float* ffn_gamma   = (const float*)d_in[19];
    const float* ffn_in_w    = (const float*)d_in[20];
    const float* ffn_in_b    = (const float*)d_in[21];
    const float* ffn_out_w   = (const float*)d_in[22];
    const float* ffn_out_b   = (const float*)d_in[23];
    const float* score_scale = (const float*)d_in[24];
    const float* prior_scale = (const float*)d_in[25];
    const float* qss         = (const float*)d_in[26];
    float* out = (float*)d_out;

    cudaFuncSetAttribute(latent_kernel, cudaFuncAttributeMaxDynamicSharedMemorySize, K1_SMEM_BYTES);
    cudaFuncSetAttribute(main_kernel,   cudaFuncAttributeMaxDynamicSharedMemorySize, K2_SMEM_BYTES);

    latent_kernel<<<B * T, 256, K1_SMEM_BYTES>>>(
        latent, lp_gamma, lp_w, lp_b, k_w, k_b, v_w, v_b);

    main_kernel<<<dim3(F / FC, T, B), 256, K2_SMEM_BYTES>>>(
        side, basis, qn_gamma,
        qmlp_in_w, qmlp_in_b, qmlp_out_w, qmlp_out_b,
        q_w, q_b, o_w, o_b,
        ffn_gamma, ffn_in_w, ffn_in_b, ffn_out_w, ffn_out_b,
        score_scale, prior_scale, qss, out);
}

// round 3
// speedup vs baseline: 1.4410x; 1.4410x over previous
#include <cuda_runtime.h>
#include <cstdint>
#include <math.h>

typedef unsigned long long ull;

__device__ __forceinline__ ull pack2(float lo, float hi) {
    ull r; asm("mov.b64 %0, {%1, %2};" : "=l"(r) : "f"(lo), "f"(hi)); return r;
}
__device__ __forceinline__ void unpack2(ull v, float& lo, float& hi) {
    asm("mov.b64 {%0, %1}, %2;" : "=f"(lo), "=f"(hi) : "l"(v));
}
__device__ __forceinline__ ull ffma2(ull a, ull b, ull c) {
    ull d; asm("fma.rn.f32x2 %0, %1, %2, %3;" : "=l"(d) : "l"(a), "l"(b), "l"(c)); return d;
}

static constexpr int B = 8, C = 128, T = 128, F = 512, K = 64;
static constexpr int FC = 128;     // F columns per CTA in main kernel
static constexpr int PXF = 128;    // pitch (floats) for 128-wide smem tiles
static constexpr int PXK = 64;     // pitch (floats) for 64-wide smem tiles

// scratch for k/v projections of the latent path: [b*T+t][c][k]
__device__ float g_kbuf[(size_t)B * T * C * K];
__device__ float g_vbuf[(size_t)B * T * C * K];

__device__ __forceinline__ float silu_f(float g) {
    float e = __expf(-g);
    return __fdividef(g, 1.0f + e);
}

// ---------------------------------------------------------------------------
// Core SIMT GEMM, 256 threads = 8 warps.
// Warp w owns rows r = w + 8*i (i < RT=16); lane tx owns f-pairs tx + 32*jp.
// Weight chunk (CH cols) staged in smem as DUPLICATED (w,w) ull pairs; the
// inner-loop weight read Wts[(ty+8i)*PW+cc] is a true warp-broadcast LDS.64
// (all lanes same address -> 1 crossbar phase, no pack MOVs).
// X read: LDS.64, lanes consecutive -> conflict-free.
// Register-prefetch of the next weight chunk hides LDG latency.
// ---------------------------------------------------------------------------
template <int RT, int NP, int PX, int CH>
__device__ __forceinline__ void gemm_core(
    const float* __restrict__ Wglob,   // [RT*8][128] row-major
    const float* __restrict__ Xin,     // smem tile, pitch PX floats
    ull* __restrict__ Wts,             // smem staging, (RT*8) x (CH+1) ull
    ull acc[RT][NP], int tid)
{
    const int tx = tid & 31, ty = tid >> 5;
    constexpr int R  = RT * 8;
    constexpr int PW = CH + 1;
    constexpr int C4 = CH / 4;                 // float4 per row per chunk
    constexpr int PT = (R * C4) / 256;
    static_assert((R * C4) % 256 == 0, "staging divisibility");

    float4 pf[PT];
    #pragma unroll
    for (int p = 0; p < PT; ++p) {
        int idx = tid + p * 256;
        int r = idx / C4, q = idx % C4;
        pf[p] = *reinterpret_cast<const float4*>(Wglob + r * 128 + q * 4);
    }

    for (int c0 = 0; c0 < 128; c0 += CH) {
        __syncthreads();   // prior readers of Wts are done
        #pragma unroll
        for (int p = 0; p < PT; ++p) {
            int idx = tid + p * 256;
            int r = idx / C4, q = idx % C4;
            ull* d = Wts + r * PW + q * 4;
            d[0] = pack2(pf[p].x, pf[p].x);
            d[1] = pack2(pf[p].y, pf[p].y);
            d[2] = pack2(pf[p].z, pf[p].z);
            d[3] = pack2(pf[p].w, pf[p].w);
        }
        __syncthreads();
        if (c0 + CH < 128) {   // prefetch next chunk while computing this one
            #pragma unroll
            for (int p = 0; p < PT; ++p) {
                int idx = tid + p * 256;
                int r = idx / C4, q = idx % C4;
                pf[p] = *reinterpret_cast<const float4*>(Wglob + r * 128 + (c0 + CH) + q * 4);
            }
        }
        #pragma unroll 4
        for (int cc = 0; cc < CH; ++cc) {
            const float* xrow = Xin + (c0 + cc) * PX;
            ull xp[NP];
            #pragma unroll
            for (int jp = 0; jp < NP; ++jp)
                xp[jp] = *reinterpret_cast<const ull*>(xrow + 2 * (tx + 32 * jp));
            #pragma unroll
            for (int i = 0; i < RT; ++i) {
                ull wp = Wts[(ty + 8 * i) * PW + cc];   // warp-broadcast
                #pragma unroll
                for (int jp = 0; jp < NP; ++jp)
                    acc[i][jp] = ffma2(wp, xp[jp], acc[i][jp]);
            }
        }
    }
}

// ---------------------------------------------------------------------------
// Kernel 1: latent path. One CTA per (b,t) frame, 2 CTAs/SM.
// ---------------------------------------------------------------------------
static constexpr int K1_XL = 0;
static constexpr int K1_LH = 128 * PXK;                 // 8192
static constexpr int K1_WT = K1_LH + 128 * PXK;         // 16384 (float offset)
static constexpr int K1_WT_ULL = 128 * 17;              // 2176 ull
static constexpr int K1_RS = K1_WT + 2 * K1_WT_ULL;     // float offset
static constexpr int K1_SMEM_BYTES = (K1_RS + 64) * 4;

__global__ void __launch_bounds__(256, 2) latent_kernel(
    const float* __restrict__ latent, const float* __restrict__ lp_gamma,
    const float* __restrict__ lp_w,   const float* __restrict__ lp_b,
    const float* __restrict__ k_w,    const float* __restrict__ k_b,
    const float* __restrict__ v_w,    const float* __restrict__ v_b)
{
    extern __shared__ float sm[];
    float* Xl  = sm + K1_XL;
    float* Lh  = sm + K1_LH;
    ull*   Wts = reinterpret_cast<ull*>(sm + K1_WT);
    float* rstd = sm + K1_RS;
    const int tid = threadIdx.x;
    const int frame = blockIdx.x;            // b*T + t
    const int b = frame / T, t = frame % T;
    const int tx = tid & 31, ty = tid >> 5;

    // load latent frame [128][64] (rows strided T*K in global)
    const float* src = latent + ((size_t)b * C * T + t) * K;
    #pragma unroll
    for (int idx = tid; idx < 128 * 16; idx += 256) {
        int r = idx >> 4, q = idx & 15;
        float4 v = *reinterpret_cast<const float4*>(src + (size_t)r * (T * K) + q * 4);
        *reinterpret_cast<float4*>(Xl + r * PXK + q * 4) = v;
    }
    __syncthreads();
    if (tid < 64) {
        float s0 = 0, s1 = 0, s2 = 0, s3 = 0;
        for (int c = 0; c < 128; c += 4) {
            float a = Xl[c * PXK + tid], bb = Xl[(c + 1) * PXK + tid];
            float cc = Xl[(c + 2) * PXK + tid], dd = Xl[(c + 3) * PXK + tid];
            s0 += a * a; s1 += bb * bb; s2 += cc * cc; s3 += dd * dd;
        }
        rstd[tid] = rsqrtf((s0 + s1 + s2 + s3) * (1.0f / 128.0f) + 1e-6f);
    }
    __syncthreads();
    #pragma unroll
    for (int idx = tid; idx < 128 * 16; idx += 256) {
        int r = idx >> 4, q = idx & 15;
        float g = lp_gamma[r];
        float* d = Xl + r * PXK + q * 4;
        d[0] *= rstd[q * 4 + 0] * g; d[1] *= rstd[q * 4 + 1] * g;
        d[2] *= rstd[q * 4 + 2] * g; d[3] *= rstd[q * 4 + 3] * g;
    }
    // (gemm_core begins with __syncthreads)

    // latent_h = silu(lp_w @ Xn + lp_b)
    {
        ull acc[16][1] = {};
        gemm_core<16, 1, PXK, 16>(lp_w, Xl, Wts, acc, tid);
        #pragma unroll
        for (int i = 0; i < 16; ++i) {
            int r = ty + 8 * i;
            float bias = lp_b[r];
            float lo, hi; unpack2(acc[i][0], lo, hi);
            int fl = 2 * tx;
            Lh[r * PXK + fl]     = silu_f(lo + bias);
            Lh[r * PXK + fl + 1] = silu_f(hi + bias);
        }
    }
    // k projection -> g_kbuf
    {
        ull acc[16][1] = {};
        gemm_core<16, 1, PXK, 16>(k_w, Lh, Wts, acc, tid);
        float* dst = g_kbuf + (size_t)frame * (C * K);
        #pragma unroll
        for (int i = 0; i < 16; ++i) {
            int r = ty + 8 * i;
            float bias = k_b[r];
            float lo, hi; unpack2(acc[i][0], lo, hi);
            *reinterpret_cast<float2*>(dst + r * K + 2 * tx) = make_float2(lo + bias, hi + bias);
        }
    }
    // v projection -> g_vbuf
    {
        ull acc[16][1] = {};
        gemm_core<16, 1, PXK, 16>(v_w, Lh, Wts, acc, tid);
        float* dst = g_vbuf + (size_t)frame * (C * K);
        #pragma unroll
        for (int i = 0; i < 16; ++i) {
            int r = ty + 8 * i;
            float bias = v_b[r];
            float lo, hi; unpack2(acc[i][0], lo, hi);
            *reinterpret_cast<float2*>(dst + r * K + 2 * tx) = make_float2(lo + bias, hi + bias);
        }
    }
}

// ---------------------------------------------------------------------------
// Kernel 2: fused side path + attention + FFN. One CTA per (b, t, f-chunk).
// ---------------------------------------------------------------------------
static constexpr int K2_XS = 0;
static constexpr int K2_HS = 128 * PXF;                 // 16384
static constexpr int K2_KS = K2_HS + 128 * PXF;         // 32768
static constexpr int K2_VS = K2_KS + 128 * PXK;         // 40960
static constexpr int K2_WT = K2_VS + 128 * PXK;         // 49152 (float offset)
static constexpr int K2_WT_ULL = 128 * 17;              // 2176 ull
static constexpr int K2_RS = K2_WT + 2 * K2_WT_ULL;     // 53504
static constexpr int K2_SMEM_BYTES = (K2_RS + 128) * 4; // 214,528 B

__global__ void __launch_bounds__(256, 1) main_kernel(
    const float* __restrict__ side,      const float* __restrict__ basis,
    const float* __restrict__ qn_gamma,
    const float* __restrict__ qmlp_in_w, const float* __restrict__ qmlp_in_b,
    const float* __restrict__ qmlp_out_w,const float* __restrict__ qmlp_out_b,
    const float* __restrict__ q_w,       const float* __restrict__ q_b,
    const float* __restrict__ o_w,       const float* __restrict__ o_b,
    const float* __restrict__ ffn_gamma,
    const float* __restrict__ ffn_in_w,  const float* __restrict__ ffn_in_b,
    const float* __restrict__ ffn_out_w, const float* __restrict__ ffn_out_b,
    const float* __restrict__ score_scale, const float* __restrict__ prior_scale,
    const float* __restrict__ query_skip_scale,
    float* __restrict__ out)
{
    extern __shared__ float sm[];
    float* Xs  = sm + K2_XS;
    float* Hs  = sm + K2_HS;
    float* Ks  = sm + K2_KS;
    float* Vs  = sm + K2_VS;
    ull*   Wts = reinterpret_cast<ull*>(sm + K2_WT);
    float* rstd = sm + K2_RS;

    const int tid = threadIdx.x;
    const int fc = blockIdx.x;      // 0..3
    const int t  = blockIdx.y;
    const int b  = blockIdx.z;
    const int f0 = fc * FC;
    const int tx = tid & 31, ty = tid >> 5;
    const int frame = b * T + t;

    // ---- load k/v frame into smem (linear copy, pitch == K) ----
    {
        const float4* ksrc = reinterpret_cast<const float4*>(g_kbuf + (size_t)frame * (C * K));
        const float4* vsrc = reinterpret_cast<const float4*>(g_vbuf + (size_t)frame * (C * K));
        float4* kdst = reinterpret_cast<float4*>(Ks);
        float4* vdst = reinterpret_cast<float4*>(Vs);
        #pragma unroll
        for (int idx = tid; idx < 128 * 16; idx += 256) {
            kdst[idx] = ksrc[idx];
            vdst[idx] = vsrc[idx];
        }
    }
    // ---- load side chunk [128][128] ----
    const float* sbase = side + ((size_t)b * C * T + t) * F + f0;
    #pragma unroll
    for (int idx = tid; idx < 128 * 32; idx += 256) {
        int r = idx >> 5, q = idx & 31;
        float4 v = *reinterpret_cast<const float4*>(sbase + (size_t)r * (T * F) + q * 4);
        *reinterpret_cast<float4*>(Xs + r * PXF + q * 4) = v;
    }
    __syncthreads();
    // ---- rmsnorm (axis C) ----
    if (tid < 128) {
        float s0 = 0, s1 = 0, s2 = 0, s3 = 0;
        for (int c = 0; c < 128; c += 4) {
            float a = Xs[c * PXF + tid], bb = Xs[(c + 1) * PXF + tid];
            float cc = Xs[(c + 2) * PXF + tid], dd = Xs[(c + 3) * PXF + tid];
            s0 += a * a; s1 += bb * bb; s2 += cc * cc; s3 += dd * dd;
        }
        rstd[tid] = rsqrtf((s0 + s1 + s2 + s3) * (1.0f / 128.0f) + 1e-6f);
    }
    __syncthreads();
    #pragma unroll
    for (int idx = tid; idx < 128 * 32; idx += 256) {
        int r = idx >> 5, q = idx & 31;
        float g = qn_gamma[r];
        float* d = Xs + r * PXF + q * 4;
        d[0] *= rstd[q * 4 + 0] * g; d[1] *= rstd[q * 4 + 1] * g;
        d[2] *= rstd[q * 4 + 2] * g; d[3] *= rstd[q * 4 + 3] * g;
    }

    // ---- GEMM1: qmlp_in (gated, two 128-row passes) -> m in Hs ----
    {   // pass 1: gate rows (W rows 128..255) -> silu(g) into Hs
        ull acc[16][2] = {};
        gemm_core<16, 2, PXF, 16>(qmlp_in_w + 128 * 128, Xs, Wts, acc, tid);
        #pragma unroll
        for (int i = 0; i < 16; ++i) {
            int r = ty + 8 * i;
            float bg = qmlp_in_b[r + 128];
            #pragma unroll
            for (int jp = 0; jp < 2; ++jp) {
                float g0, g1; unpack2(acc[i][jp], g0, g1);
                int fl = 2 * (tx + 32 * jp);
                Hs[r * PXF + fl]     = silu_f(g0 + bg);
                Hs[r * PXF + fl + 1] = silu_f(g1 + bg);
            }
        }
    }
    {   // pass 2: a rows; m = (a+b) * silu(g)  (same-thread same-slot in Hs)
        ull acc[16][2] = {};
        gemm_core<16, 2, PXF, 16>(qmlp_in_w, Xs, Wts, acc, tid);
        #pragma unroll
        for (int i = 0; i < 16; ++i) {
            int r = ty + 8 * i;
            float ba = qmlp_in_b[r];
            #pragma unroll
            for (int jp = 0; jp < 2; ++jp) {
                float a0, a1; unpack2(acc[i][jp], a0, a1);
                int fl = 2 * (tx + 32 * jp);
                Hs[r * PXF + fl]     = (a0 + ba) * Hs[r * PXF + fl];
                Hs[r * PXF + fl + 1] = (a1 + ba) * Hs[r * PXF + fl + 1];
            }
        }
    }
    // ---- GEMM2: qmlp_out -> query_h in Xs ----
    {
        ull acc[16][2] = {};
        gemm_core<16, 2, PXF, 16>(qmlp_out_w, Hs, Wts, acc, tid);
        #pragma unroll
        for (int i = 0; i < 16; ++i) {
            int r = ty + 8 * i;
            float bias = qmlp_out_b[r];
            #pragma unroll
            for (int jp = 0; jp < 2; ++jp) {
                float lo, hi; unpack2(acc[i][jp], lo, hi);
                int fl = 2 * (tx + 32 * jp);
                Xs[r * PXF + fl] = lo + bias; Xs[r * PXF + fl + 1] = hi + bias;
            }
        }
    }
    // ---- GEMM3: q projection -> Hs ----
    {
        ull acc[16][2] = {};
        gemm_core<16, 2, PXF, 16>(q_w, Xs, Wts, acc, tid);
        #pragma unroll
        for (int i = 0; i < 16; ++i) {
            int r = ty + 8 * i;
            float bias = q_b[r];
            #pragma unroll
            for (int jp = 0; jp < 2; ++jp) {
                float lo, hi; unpack2(acc[i][jp], lo, hi);
                int fl = 2 * (tx + 32 * jp);
                Hs[r * PXF + fl] = lo + bias; Hs[r * PXF + fl + 1] = hi + bias;
            }
        }
    }
    __syncthreads();   // q fully in Hs before scores

    // ---- scores [f][k] + softmax over k ----
    const int kg = tid & 7, fg = tid >> 3;    // k-octet lives in lane bits 0..2
    float wgt[4][8];
    {
        ull sacc[4][4] = {};
        #pragma unroll 4
        for (int c = 0; c < 128; ++c) {
            const float* qrow = Hs + c * PXF + fg * 4;
            const float* krow = Ks + c * PXK + kg * 8;
            ull kp[4];
            #pragma unroll
            for (int jp = 0; jp < 4; ++jp)
                kp[jp] = *reinterpret_cast<const ull*>(krow + 2 * jp);
            #pragma unroll
            for (int i = 0; i < 4; ++i) {
                float qv = qrow[i];
                ull qp = pack2(qv, qv);
                #pragma unroll
                for (int jp = 0; jp < 4; ++jp)
                    sacc[i][jp] = ffma2(qp, kp[jp], sacc[i][jp]);
            }
        }
        const float ssc = *score_scale, psc = *prior_scale;
        #pragma unroll
        for (int i = 0; i < 4; ++i) {
            float s[8];
            #pragma unroll
            for (int jp = 0; jp < 4; ++jp) unpack2(sacc[i][jp], s[2 * jp], s[2 * jp + 1]);
            int fglob = f0 + fg * 4 + i;
            #pragma unroll
            for (int j = 0; j < 8; ++j)
                s[j] = s[j] * ssc + basis[(kg * 8 + j) * F + fglob] * psc;
            float m = s[0];
            #pragma unroll
            for (int j = 1; j < 8; ++j) m = fmaxf(m, s[j]);
            #pragma unroll
            for (int d = 1; d < 8; d <<= 1) m = fmaxf(m, __shfl_xor_sync(0xffffffffu, m, d));
            float sum = 0;
            #pragma unroll
            for (int j = 0; j < 8; ++j) { float e = __expf(s[j] - m); wgt[i][j] = e; sum += e; }
            #pragma unroll
            for (int d = 1; d < 8; d <<= 1) sum += __shfl_xor_sync(0xffffffffu, sum, d);
            float inv = __frcp_rn(sum);
            #pragma unroll
            for (int j = 0; j < 8; ++j) wgt[i][j] *= inv;
        }
    }
    __syncthreads();   // all reads of Ks done
    {   // store weights transposed into the dead Ks region: Ws[k][f], pitch PXF
        float* Ws = Ks;
        #pragma unroll
        for (int i = 0; i < 4; ++i) {
            int fl = fg * 4 + i;
            #pragma unroll
            for (int j = 0; j < 8; ++j) Ws[(kg * 8 + j) * PXF + fl] = wgt[i][j];
        }
    }
    __syncthreads();
    // ---- attended[c][f] = sum_k Ws[k][f] * Vs[c][k] -> Hs ----
    {
        ull acc[16][2] = {};
        const float* Ws = Ks;
        #pragma unroll 4
        for (int kk = 0; kk < 64; ++kk) {
            ull xp[2];
            #pragma unroll
            for (int jp = 0; jp < 2; ++jp)
                xp[jp] = *reinterpret_cast<const ull*>(Ws + kk * PXF + 2 * (tx + 32 * jp));
            #pragma unroll
            for (int i = 0; i < 16; ++i) {
                float v = Vs[(ty + 8 * i) * PXK + kk];   // warp-broadcast
                ull vp = pack2(v, v);
                #pragma unroll
                for (int jp = 0; jp < 2; ++jp)
                    acc[i][jp] = ffma2(vp, xp[jp], acc[i][jp]);
            }
        }
        #pragma unroll
        for (int i = 0; i < 16; ++i) {
            int r = ty + 8 * i;
            #pragma unroll
            for (int jp = 0; jp < 2; ++jp) {
                float lo, hi; unpack2(acc[i][jp], lo, hi);
                int fl = 2 * (tx + 32 * jp);
                Hs[r * PXF + fl] = lo; Hs[r * PXF + fl + 1] = hi;
            }
        }
    }
    // ---- GEMM4: hidden = o_w @ attended + o_b + qss*query_h -> Xs (in place) ----
    {
        ull acc[16][2] = {};
        gemm_core<16, 2, PXF, 16>(o_w, Hs, Wts, acc, tid);
        const float qs = *query_skip_scale;
        #pragma unroll
        for (int i = 0; i < 16; ++i) {
            int r = ty + 8 * i;
            float bias = o_b[r];
            #pragma unroll
            for (int jp = 0; jp < 2; ++jp) {
                float lo, hi; unpack2(acc[i][jp], lo, hi);
                int fl = 2 * (tx + 32 * jp);
                lo += bias + qs * Xs[r * PXF + fl];
                hi += bias + qs * Xs[r * PXF + fl + 1];
                Xs[r * PXF + fl] = lo; Xs[r * PXF + fl + 1] = hi;
            }
        }
    }
    __syncthreads();
    // ---- FFN rmsnorm: Hs = rmsnorm(Xs)*ffn_gamma ----
    if (tid < 128) {
        float s0 = 0, s1 = 0, s2 = 0, s3 = 0;
        for (int c = 0; c < 128; c += 4) {
            float a = Xs[c * PXF + tid], bb = Xs[(c + 1) * PXF + tid];
            float cc = Xs[(c + 2) * PXF + tid], dd = Xs[(c + 3) * PXF + tid];
            s0 += a * a; s1 += bb * bb; s2 += cc * cc; s3 += dd * dd;
        }
        rstd[tid] = rsqrtf((s0 + s1 + s2 + s3) * (1.0f / 128.0f) + 1e-6f);
    }
    __syncthreads();
    #pragma unroll
    for (int idx = tid; idx < 128 * 32; idx += 256) {
        int r = idx >> 5, q = idx & 31;
        float g = ffn_gamma[r];
        const float* s = Xs + r * PXF + q * 4;
        float* d = Hs + r * PXF + q * 4;
        d[0] = s[0] * rstd[q * 4 + 0] * g; d[1] = s[1] * rstd[q * 4 + 1] * g;
        d[2] = s[2] * rstd[q * 4 + 2] * g; d[3] = s[3] * rstd[q * 4 + 3] * g;
    }
    // ---- GEMM5: ffn_in (gated, two passes), intermediate in Gb = Ks+Vs region ----
    float* Gb = Ks;   // 128 x 128 floats spanning dead Ks+Vs (contiguous 64KB)
    {   // pass 1: gate rows -> silu into Gb
        ull acc[16][2] = {};
        gemm_core<16, 2, PXF, 16>(ffn_in_w + 128 * 128, Hs, Wts, acc, tid);
        #pragma unroll
        for (int i = 0; i < 16; ++i) {
            int r = ty + 8 * i;
            float bg = ffn_in_b[r + 128];
            #pragma unroll
            for (int jp = 0; jp < 2; ++jp) {
                float g0, g1; unpack2(acc[i][jp], g0, g1);
                int fl = 2 * (tx + 32 * jp);
                Gb[r * PXF + fl]     = silu_f(g0 + bg);
                Gb[r * PXF + fl + 1] = silu_f(g1 + bg);
            }
        }
    }
    {   // pass 2: a rows; m2 = (a+b)*silu(g) into Gb (same-thread same-slot)
        ull acc[16][2] = {};
        gemm_core<16, 2, PXF, 16>(ffn_in_w, Hs, Wts, acc, tid);
        #pragma unroll
        for (int i = 0; i < 16; ++i) {
            int r = ty + 8 * i;
            float ba = ffn_in_b[r];
            #pragma unroll
            for (int jp = 0; jp < 2; ++jp) {
                float a0, a1; unpack2(acc[i][jp], a0, a1);
                int fl = 2 * (tx + 32 * jp);
                Gb[r * PXF + fl]     = (a0 + ba) * Gb[r * PXF + fl];
                Gb[r * PXF + fl + 1] = (a1 + ba) * Gb[r * PXF + fl + 1];
            }
        }
    }
    // ---- GEMM6: out = ffn_out @ m2 + ffn_out_b + hidden -> global ----
    {
        ull acc[16][2] = {};
        gemm_core<16, 2, PXF, 16>(ffn_out_w, Gb, Wts, acc, tid);
        float* obase = out + ((size_t)b * C * T + t) * F + f0;
        #pragma unroll
        for (int i = 0; i < 16; ++i) {
            int r = ty + 8 * i;
            float bias = ffn_out_b[r];
            #pragma unroll
            for (int jp = 0; jp < 2; ++jp) {
                float lo, hi; unpack2(acc[i][jp], lo, hi);
                int fl = 2 * (tx + 32 * jp);
                lo += bias + Xs[r * PXF + fl];
                hi += bias + Xs[r * PXF + fl + 1];
                *reinterpret_cast<float2*>(obase + (size_t)r * (T * F) + fl) = make_float2(lo, hi);
            }
        }
    }
}

// ---------------------------------------------------------------------------
extern "C" void kernel_launch(void* const* d_in, const int* in_sizes, int n_in,
                              void* d_out, int out_size)
{
    const float* latent      = (const float*)d_in[0];
    const float* side        = (const float*)d_in[1];
    const float* basis       = (const float*)d_in[2];
    const float* lp_gamma    = (const float*)d_in[3];
    const float* lp_w        = (const float*)d_in[4];
    const float* lp_b        = (const float*)d_in[5];
    const float* qn_gamma    = (const float*)d_in[6];
    const float* qmlp_in_w   = (const float*)d_in[7];
    const float* qmlp_in_b   = (const float*)d_in[8];
    const float* qmlp_out_w  = (const float*)d_in[9];
    const float* qmlp_out_b  = (const float*)d_in[10];
    const float* q_w         = (const float*)d_in[11];
    const float* q_b         = (const float*)d_in[12];
    const float* k_w         = (const float*)d_in[13];
    const float* k_b         = (const float*)d_in[14];
    const float* v_w         = (const float*)d_in[15];
    const float* v_b         = (const float*)d_in[16];
    const float* o_w         = (const float*)d_in[17];
    const float* o_b         = (const float*)d_in[18];
    const float* ffn_gamma   = (const float*)d_in[19];
    const float* ffn_in_w    = (const float*)d_in[20];
    const float* ffn_in_b    = (const float*)d_in[21];
    const float* ffn_out_w   = (const float*)d_in[22];
    const float* ffn_out_b   = (const float*)d_in[23];
    const float* score_scale = (const float*)d_in[24];
    const float* prior_scale = (const float*)d_in[25];
    const float* qss         = (const float*)d_in[26];
    float* out = (float*)d_out;

    cudaFuncSetAttribute(latent_kernel, cudaFuncAttributeMaxDynamicSharedMemorySize, K1_SMEM_BYTES);
    cudaFuncSetAttribute(main_kernel,   cudaFuncAttributeMaxDynamicSharedMemorySize, K2_SMEM_BYTES);

    latent_kernel<<<B * T, 256, K1_SMEM_BYTES>>>(
        latent, lp_gamma, lp_w, lp_b, k_w, k_b, v_w, v_b);

    main_kernel<<<dim3(F / FC, T, B), 256, K2_SMEM_BYTES>>>(
        side, basis, qn_gamma,
        qmlp_in_w, qmlp_in_b, qmlp_out_w, qmlp_out_b,
        q_w, q_b, o_w, o_b,
        ffn_gamma, ffn_in_w, ffn_in_b, ffn_out_w, ffn_out_b,
        score_scale, prior_scale, qss, out);
}

// round 4
// speedup vs baseline: 1.5724x; 1.0912x over previous
#include <cuda_runtime.h>
#include <cstdint>
#include <math.h>

typedef unsigned long long ull;

__device__ __forceinline__ ull pack2(float lo, float hi) {
    ull r; asm("mov.b64 %0, {%1, %2};" : "=l"(r) : "f"(lo), "f"(hi)); return r;
}
__device__ __forceinline__ void unpack2(ull v, float& lo, float& hi) {
    asm("mov.b64 {%0, %1}, %2;" : "=f"(lo), "=f"(hi) : "l"(v));
}
__device__ __forceinline__ ull ffma2(ull a, ull b, ull c) {
    ull d; asm("fma.rn.f32x2 %0, %1, %2, %3;" : "=l"(d) : "l"(a), "l"(b), "l"(c)); return d;
}

static constexpr int B = 8, C = 128, T = 128, F = 512, K = 64;
static constexpr int FC = 128;     // F columns per CTA in main kernel
static constexpr int PXF = 128;    // pitch (floats) for 128-wide smem tiles
static constexpr int PXK = 68;     // pitch (floats) for 64-wide smem tiles (bank-skewed)

// scratch for k/v projections of the latent path: [b*T+t][c][k]
__device__ float g_kbuf[(size_t)B * T * C * K];
__device__ float g_vbuf[(size_t)B * T * C * K];

__device__ __forceinline__ float silu_f(float g) {
    float e = __expf(-g);
    return __fdividef(g, 1.0f + e);
}

// ---------------------------------------------------------------------------
// Core SIMT GEMM, 256 threads (16x16 map). out[r][f] = sum_c W[r][c]*X[c][f].
// tx = tid&15 owns f-pairs fl = 2*(tx+16*jp), jp < NP.
// ty = tid>>4 owns rows r = ty + 16*i, i < RT.
// Weights staged in smem DUPLICATED (w,w) and PAIR-INTERLEAVED:
//   Wts[(r>>1)*PW2 + 2*cc + (r&1)]  (PW2 = 2*CH+2)
// so a warp's two ty rows are 8 bytes apart -> every w-load is a 1-wavefront
// 2-address broadcast LDS.64 with no inner-loop packing MOVs.
// x-loads: lanes 16..31 mirror lanes 0..15 -> 128B window, 1 wavefront.
// Next weight chunk is register-prefetched to hide LDG latency.
// ---------------------------------------------------------------------------
template <int RT, int NP, int PX, int CH>
__device__ __forceinline__ void gemm_core(
    const float* __restrict__ Wglob,   // [RT*16][128] row-major
    const float* __restrict__ Xin,     // smem tile, pitch PX floats
    ull* __restrict__ Wts,             // smem staging, (RT*8) x PW2 ull
    ull acc[RT][NP], int tid)
{
    const int tx = tid & 15, ty = tid >> 4;
    constexpr int R   = RT * 16;
    constexpr int PW2 = 2 * CH + 2;
    constexpr int C4  = CH / 4;
    constexpr int PT  = (R * C4) / 256;
    static_assert((R * C4) % 256 == 0, "staging divisibility");

    const int wbase = (ty >> 1) * PW2 + (ty & 1);

    float4 pf[PT];
    #pragma unroll
    for (int p = 0; p < PT; ++p) {
        int idx = tid + p * 256;
        int r = idx / C4, q = idx % C4;
        pf[p] = *reinterpret_cast<const float4*>(Wglob + r * 128 + q * 4);
    }

    for (int c0 = 0; c0 < 128; c0 += CH) {
        __syncthreads();   // prior readers of Wts are done
        #pragma unroll
        for (int p = 0; p < PT; ++p) {
            int idx = tid + p * 256;
            int r = idx / C4, q = idx % C4;
            ull* d = Wts + (r >> 1) * PW2 + (r & 1) + 2 * (q * 4);
            d[0] = pack2(pf[p].x, pf[p].x);
            d[2] = pack2(pf[p].y, pf[p].y);
            d[4] = pack2(pf[p].z, pf[p].z);
            d[6] = pack2(pf[p].w, pf[p].w);
        }
        __syncthreads();
        if (c0 + CH < 128) {   // prefetch next chunk while computing this one
            #pragma unroll
            for (int p = 0; p < PT; ++p) {
                int idx = tid + p * 256;
                int r = idx / C4, q = idx % C4;
                pf[p] = *reinterpret_cast<const float4*>(Wglob + r * 128 + (c0 + CH) + q * 4);
            }
        }
        #pragma unroll 4
        for (int cc = 0; cc < CH; ++cc) {
            const float* xrow = Xin + (c0 + cc) * PX;
            ull xp[NP];
            #pragma unroll
            for (int jp = 0; jp < NP; ++jp)
                xp[jp] = *reinterpret_cast<const ull*>(xrow + 2 * (tx + 16 * jp));
            #pragma unroll
            for (int i = 0; i < RT; ++i) {
                ull wp = Wts[wbase + i * (8 * PW2) + 2 * cc];   // 1-wf broadcast
                #pragma unroll
                for (int jp = 0; jp < NP; ++jp)
                    acc[i][jp] = ffma2(wp, xp[jp], acc[i][jp]);
            }
        }
    }
}

// ---------------------------------------------------------------------------
// Kernel 1: latent path. One CTA per (b,t) frame, 2 CTAs/SM.
// ---------------------------------------------------------------------------
static constexpr int K1_XL = 0;
static constexpr int K1_LH = 128 * PXK;                 // 8704
static constexpr int K1_WT = K1_LH + 128 * PXK;         // 17408 (float offset)
static constexpr int K1_WT_ULL = 64 * 34;               // 2176 ull
static constexpr int K1_RS = K1_WT + 2 * K1_WT_ULL;     // 21760
static constexpr int K1_SMEM_BYTES = (K1_RS + 64) * 4;  // 87,296 B

__global__ void __launch_bounds__(256, 2) latent_kernel(
    const float* __restrict__ latent, const float* __restrict__ lp_gamma,
    const float* __restrict__ lp_w,   const float* __restrict__ lp_b,
    const float* __restrict__ k_w,    const float* __restrict__ k_b,
    const float* __restrict__ v_w,    const float* __restrict__ v_b)
{
    extern __shared__ float sm[];
    float* Xl  = sm + K1_XL;
    float* Lh  = sm + K1_LH;
    ull*   Wts = reinterpret_cast<ull*>(sm + K1_WT);
    float* rstd = sm + K1_RS;
    const int tid = threadIdx.x;
    const int frame = blockIdx.x;            // b*T + t
    const int b = frame / T, t = frame % T;
    const int tx = tid & 15, ty = tid >> 4;

    // load latent frame [128][64] (rows strided T*K in global)
    const float* src = latent + ((size_t)b * C * T + t) * K;
    #pragma unroll
    for (int idx = tid; idx < 128 * 16; idx += 256) {
        int r = idx >> 4, q = idx & 15;
        float4 v = *reinterpret_cast<const float4*>(src + (size_t)r * (T * K) + q * 4);
        *reinterpret_cast<float4*>(Xl + r * PXK + q * 4) = v;
    }
    __syncthreads();
    if (tid < 64) {
        float s0 = 0, s1 = 0, s2 = 0, s3 = 0;
        for (int c = 0; c < 128; c += 4) {
            float a = Xl[c * PXK + tid], bb = Xl[(c + 1) * PXK + tid];
            float cc = Xl[(c + 2) * PXK + tid], dd = Xl[(c + 3) * PXK + tid];
            s0 += a * a; s1 += bb * bb; s2 += cc * cc; s3 += dd * dd;
        }
        rstd[tid] = rsqrtf((s0 + s1 + s2 + s3) * (1.0f / 128.0f) + 1e-6f);
    }
    __syncthreads();
    #pragma unroll
    for (int idx = tid; idx < 128 * 16; idx += 256) {
        int r = idx >> 4, q = idx & 15;
        float g = lp_gamma[r];
        float* d = Xl + r * PXK + q * 4;
        d[0] *= rstd[q * 4 + 0] * g; d[1] *= rstd[q * 4 + 1] * g;
        d[2] *= rstd[q * 4 + 2] * g; d[3] *= rstd[q * 4 + 3] * g;
    }
    // (gemm_core begins with __syncthreads)

    // latent_h = silu(lp_w @ Xn + lp_b)
    {
        ull acc[8][2] = {};
        gemm_core<8, 2, PXK, 16>(lp_w, Xl, Wts, acc, tid);
        #pragma unroll
        for (int i = 0; i < 8; ++i) {
            int r = ty + 16 * i;
            float bias = lp_b[r];
            #pragma unroll
            for (int jp = 0; jp < 2; ++jp) {
                float lo, hi; unpack2(acc[i][jp], lo, hi);
                int fl = 2 * (tx + 16 * jp);
                Lh[r * PXK + fl]     = silu_f(lo + bias);
                Lh[r * PXK + fl + 1] = silu_f(hi + bias);
            }
        }
    }
    // k projection -> g_kbuf
    {
        ull acc[8][2] = {};
        gemm_core<8, 2, PXK, 16>(k_w, Lh, Wts, acc, tid);
        float* dst = g_kbuf + (size_t)frame * (C * K);
        #pragma unroll
        for (int i = 0; i < 8; ++i) {
            int r = ty + 16 * i;
            float bias = k_b[r];
            #pragma unroll
            for (int jp = 0; jp < 2; ++jp) {
                float lo, hi; unpack2(acc[i][jp], lo, hi);
                int fl = 2 * (tx + 16 * jp);
                *reinterpret_cast<float2*>(dst + r * K + fl) = make_float2(lo + bias, hi + bias);
            }
        }
    }
    // v projection -> g_vbuf
    {
        ull acc[8][2] = {};
        gemm_core<8, 2, PXK, 16>(v_w, Lh, Wts, acc, tid);
        float* dst = g_vbuf + (size_t)frame * (C * K);
        #pragma unroll
        for (int i = 0; i < 8; ++i) {
            int r = ty + 16 * i;
            float bias = v_b[r];
            #pragma unroll
            for (int jp = 0; jp < 2; ++jp) {
                float lo, hi; unpack2(acc[i][jp], lo, hi);
                int fl = 2 * (tx + 16 * jp);
                *reinterpret_cast<float2*>(dst + r * K + fl) = make_float2(lo + bias, hi + bias);
            }
        }
    }
}

// ---------------------------------------------------------------------------
// Kernel 2: fused side path + attention + FFN. One CTA per (b, t, f-chunk).
// ---------------------------------------------------------------------------
static constexpr int K2_XS = 0;
static constexpr int K2_HS = 128 * PXF;                 // 16384
static constexpr int K2_KS = K2_HS + 128 * PXF;         // 32768
static constexpr int K2_VS = K2_KS + 128 * PXK;         // 41472
static constexpr int K2_WT = K2_VS + 128 * PXK;         // 50176 (float offset, 8B-aligned)
static constexpr int K2_WT_ULL = 64 * 34;               // 2176 ull
static constexpr int K2_RS = K2_WT + 2 * K2_WT_ULL;     // 54528
static constexpr int K2_SMEM_BYTES = (K2_RS + 128) * 4; // 218,624 B

__global__ void __launch_bounds__(256, 1) main_kernel(
    const float* __restrict__ side,      const float* __restrict__ basis,
    const float* __restrict__ qn_gamma,
    const float* __restrict__ qmlp_in_w, const float* __restrict__ qmlp_in_b,
    const float* __restrict__ qmlp_out_w,const float* __restrict__ qmlp_out_b,
    const float* __restrict__ q_w,       const float* __restrict__ q_b,
    const float* __restrict__ o_w,       const float* __restrict__ o_b,
    const float* __restrict__ ffn_gamma,
    const float* __restrict__ ffn_in_w,  const float* __restrict__ ffn_in_b,
    const float* __restrict__ ffn_out_w, const float* __restrict__ ffn_out_b,
    const float* __restrict__ score_scale, const float* __restrict__ prior_scale,
    const float* __restrict__ query_skip_scale,
    float* __restrict__ out)
{
    extern __shared__ float sm[];
    float* Xs  = sm + K2_XS;
    float* Hs  = sm + K2_HS;
    float* Ks  = sm + K2_KS;
    float* Vs  = sm + K2_VS;
    ull*   Wts = reinterpret_cast<ull*>(sm + K2_WT);
    float* rstd = sm + K2_RS;

    const int tid = threadIdx.x;
    const int fc = blockIdx.x;      // 0..3
    const int t  = blockIdx.y;
    const int b  = blockIdx.z;
    const int f0 = fc * FC;
    const int tx = tid & 15, ty = tid >> 4;
    const int frame = b * T + t;

    // ---- load k/v frame into smem (pitch 64 -> 68) ----
    {
        const float* ksrc = g_kbuf + (size_t)frame * (C * K);
        const float* vsrc = g_vbuf + (size_t)frame * (C * K);
        #pragma unroll
        for (int idx = tid; idx < 128 * 16; idx += 256) {
            int r = idx >> 4, q = idx & 15;
            float4 kv = *reinterpret_cast<const float4*>(ksrc + r * K + q * 4);
            float4 vv = *reinterpret_cast<const float4*>(vsrc + r * K + q * 4);
            *reinterpret_cast<float4*>(Ks + r * PXK + q * 4) = kv;
            *reinterpret_cast<float4*>(Vs + r * PXK + q * 4) = vv;
        }
    }
    // ---- load side chunk [128][128] ----
    const float* sbase = side + ((size_t)b * C * T + t) * F + f0;
    #pragma unroll
    for (int idx = tid; idx < 128 * 32; idx += 256) {
        int r = idx >> 5, q = idx & 31;
        float4 v = *reinterpret_cast<const float4*>(sbase + (size_t)r * (T * F) + q * 4);
        *reinterpret_cast<float4*>(Xs + r * PXF + q * 4) = v;
    }
    __syncthreads();
    // ---- rmsnorm (axis C) ----
    if (tid < 128) {
        float s0 = 0, s1 = 0, s2 = 0, s3 = 0;
        for (int c = 0; c < 128; c += 4) {
            float a = Xs[c * PXF + tid], bb = Xs[(c + 1) * PXF + tid];
            float cc = Xs[(c + 2) * PXF + tid], dd = Xs[(c + 3) * PXF + tid];
            s0 += a * a; s1 += bb * bb; s2 += cc * cc; s3 += dd * dd;
        }
        rstd[tid] = rsqrtf((s0 + s1 + s2 + s3) * (1.0f / 128.0f) + 1e-6f);
    }
    __syncthreads();
    #pragma unroll
    for (int idx = tid; idx < 128 * 32; idx += 256) {
        int r = idx >> 5, q = idx & 31;
        float g = qn_gamma[r];
        float* d = Xs + r * PXF + q * 4;
        d[0] *= rstd[q * 4 + 0] * g; d[1] *= rstd[q * 4 + 1] * g;
        d[2] *= rstd[q * 4 + 2] * g; d[3] *= rstd[q * 4 + 3] * g;
    }

    // ---- GEMM1: qmlp_in (gated, two 128-row passes) -> m in Hs ----
    {   // pass 1: gate rows (W rows 128..255) -> silu(g) into Hs
        ull acc[8][4] = {};
        gemm_core<8, 4, PXF, 16>(qmlp_in_w + 128 * 128, Xs, Wts, acc, tid);
        #pragma unroll
        for (int i = 0; i < 8; ++i) {
            int r = ty + 16 * i;
            float bg = qmlp_in_b[r + 128];
            #pragma unroll
            for (int jp = 0; jp < 4; ++jp) {
                float g0, g1; unpack2(acc[i][jp], g0, g1);
                int fl = 2 * (tx + 16 * jp);
                Hs[r * PXF + fl]     = silu_f(g0 + bg);
                Hs[r * PXF + fl + 1] = silu_f(g1 + bg);
            }
        }
    }
    {   // pass 2: a rows; m = (a+b) * silu(g)  (same-thread same-slot in Hs)
        ull acc[8][4] = {};
        gemm_core<8, 4, PXF, 16>(qmlp_in_w, Xs, Wts, acc, tid);
        #pragma unroll
        for (int i = 0; i < 8; ++i) {
            int r = ty + 16 * i;
            float ba = qmlp_in_b[r];
            #pragma unroll
            for (int jp = 0; jp < 4; ++jp) {
                float a0, a1; unpack2(acc[i][jp], a0, a1);
                int fl = 2 * (tx + 16 * jp);
                Hs[r * PXF + fl]     = (a0 + ba) * Hs[r * PXF + fl];
                Hs[r * PXF + fl + 1] = (a1 + ba) * Hs[r * PXF + fl + 1];
            }
        }
    }
    // ---- GEMM2: qmlp_out -> query_h in Xs ----
    {
        ull acc[8][4] = {};
        gemm_core<8, 4, PXF, 16>(qmlp_out_w, Hs, Wts, acc, tid);
        #pragma unroll
        for (int i = 0; i < 8; ++i) {
            int r = ty + 16 * i;
            float bias = qmlp_out_b[r];
            #pragma unroll
            for (int jp = 0; jp < 4; ++jp) {
                float lo, hi; unpack2(acc[i][jp], lo, hi);
                int fl = 2 * (tx + 16 * jp);
                Xs[r * PXF + fl] = lo + bias; Xs[r * PXF + fl + 1] = hi + bias;
            }
        }
    }
    // ---- GEMM3: q projection -> Hs ----
    {
        ull acc[8][4] = {};
        gemm_core<8, 4, PXF, 16>(q_w, Xs, Wts, acc, tid);
        #pragma unroll
        for (int i = 0; i < 8; ++i) {
            int r = ty + 16 * i;
            float bias = q_b[r];
            #pragma unroll
            for (int jp = 0; jp < 4; ++jp) {
                float lo, hi; unpack2(acc[i][jp], lo, hi);
                int fl = 2 * (tx + 16 * jp);
                Hs[r * PXF + fl] = lo + bias; Hs[r * PXF + fl + 1] = hi + bias;
            }
        }
    }
    __syncthreads();   // q fully in Hs before scores

    // ---- scores [f][k] + softmax over k ----
    const int kg = tid & 7, fg = tid >> 3;    // k-octet lives in lane bits 0..2
    float wgt[4][8];
    {
        ull sacc[4][4] = {};
        #pragma unroll 4
        for (int c = 0; c < 128; ++c) {
            const float* qrow = Hs + c * PXF + fg * 4;
            const float* krow = Ks + c * PXK + kg * 8;
            ull kp[4];
            #pragma unroll
            for (int jp = 0; jp < 4; ++jp)
                kp[jp] = *reinterpret_cast<const ull*>(krow + 2 * jp);
            #pragma unroll
            for (int i = 0; i < 4; ++i) {
                float qv = qrow[i];
                ull qp = pack2(qv, qv);
                #pragma unroll
                for (int jp = 0; jp < 4; ++jp)
                    sacc[i][jp] = ffma2(qp, kp[jp], sacc[i][jp]);
            }
        }
        const float ssc = *score_scale, psc = *prior_scale;
        #pragma unroll
        for (int i = 0; i < 4; ++i) {
            float s[8];
            #pragma unroll
            for (int jp = 0; jp < 4; ++jp) unpack2(sacc[i][jp], s[2 * jp], s[2 * jp + 1]);
            int fglob = f0 + fg * 4 + i;
            #pragma unroll
            for (int j = 0; j < 8; ++j)
                s[j] = s[j] * ssc + basis[(kg * 8 + j) * F + fglob] * psc;
            float m = s[0];
            #pragma unroll
            for (int j = 1; j < 8; ++j) m = fmaxf(m, s[j]);
            #pragma unroll
            for (int d = 1; d < 8; d <<= 1) m = fmaxf(m, __shfl_xor_sync(0xffffffffu, m, d));
            float sum = 0;
            #pragma unroll
            for (int j = 0; j < 8; ++j) { float e = __expf(s[j] - m); wgt[i][j] = e; sum += e; }
            #pragma unroll
            for (int d = 1; d < 8; d <<= 1) sum += __shfl_xor_sync(0xffffffffu, sum, d);
            float inv = __frcp_rn(sum);
            #pragma unroll
            for (int j = 0; j < 8; ++j) wgt[i][j] *= inv;
        }
    }
    __syncthreads();   // all reads of Ks (and q in Hs) done
    {   // store weights transposed into the dead Ks region: Ws[k][f], pitch PXF
        float* Ws = Ks;
        #pragma unroll
        for (int i = 0; i < 4; ++i) {
            int fl = fg * 4 + i;
            #pragma unroll
            for (int j = 0; j < 8; ++j) Ws[(kg * 8 + j) * PXF + fl] = wgt[i][j];
        }
    }
    __syncthreads();
    // ---- attended[c][f] = sum_k Ws[k][f] * Vs[c][k] -> Hs ----
    {
        ull acc[8][4] = {};
        const float* Ws = Ks;
        #pragma unroll 4
        for (int kk = 0; kk < 64; ++kk) {
            ull xp[4];
            #pragma unroll
            for (int jp = 0; jp < 4; ++jp)
                xp[jp] = *reinterpret_cast<const ull*>(Ws + kk * PXF + 2 * (tx + 16 * jp));
            #pragma unroll
            for (int i = 0; i < 8; ++i) {
                float v = Vs[(ty + 16 * i) * PXK + kk];   // 2-addr bcast, banks differ (PXK=68)
                ull vp = pack2(v, v);
                #pragma unroll
                for (int jp = 0; jp < 4; ++jp)
                    acc[i][jp] = ffma2(vp, xp[jp], acc[i][jp]);
            }
        }
        #pragma unroll
        for (int i = 0; i < 8; ++i) {
            int r = ty + 16 * i;
            #pragma unroll
            for (int jp = 0; jp < 4; ++jp) {
                float lo, hi; unpack2(acc[i][jp], lo, hi);
                int fl = 2 * (tx + 16 * jp);
                Hs[r * PXF + fl] = lo; Hs[r * PXF + fl + 1] = hi;
            }
        }
    }
    // ---- GEMM4: hidden = o_w @ attended + o_b + qss*query_h -> Xs (in place) ----
    {
        ull acc[8][4] = {};
        gemm_core<8, 4, PXF, 16>(o_w, Hs, Wts, acc, tid);
        const float qs = *query_skip_scale;
        #pragma unroll
        for (int i = 0; i < 8; ++i) {
            int r = ty + 16 * i;
            float bias = o_b[r];
            #pragma unroll
            for (int jp = 0; jp < 4; ++jp) {
                float lo, hi; unpack2(acc[i][jp], lo, hi);
                int fl = 2 * (tx + 16 * jp);
                lo += bias + qs * Xs[r * PXF + fl];
                hi += bias + qs * Xs[r * PXF + fl + 1];
                Xs[r * PXF + fl] = lo; Xs[r * PXF + fl + 1] = hi;
            }
        }
    }
    __syncthreads();
    // ---- FFN rmsnorm: Hs = rmsnorm(Xs)*ffn_gamma ----
    if (tid < 128) {
        float s0 = 0, s1 = 0, s2 = 0, s3 = 0;
        for (int c = 0; c < 128; c += 4) {
            float a = Xs[c * PXF + tid], bb = Xs[(c + 1) * PXF + tid];
            float cc = Xs[(c + 2) * PXF + tid], dd = Xs[(c + 3) * PXF + tid];
            s0 += a * a; s1 += bb * bb; s2 += cc * cc; s3 += dd * dd;
        }
        rstd[tid] = rsqrtf((s0 + s1 + s2 + s3) * (1.0f / 128.0f) + 1e-6f);
    }
    __syncthreads();
    #pragma unroll
    for (int idx = tid; idx < 128 * 32; idx += 256) {
        int r = idx >> 5, q = idx & 31;
        float g = ffn_gamma[r];
        const float* s = Xs + r * PXF + q * 4;
        float* d = Hs + r * PXF + q * 4;
        d[0] = s[0] * rstd[q * 4 + 0] * g; d[1] = s[1] * rstd[q * 4 + 1] * g;
        d[2] = s[2] * rstd[q * 4 + 2] * g; d[3] = s[3] * rstd[q * 4 + 3] * g;
    }
    // ---- GEMM5: ffn_in (gated, two passes), intermediate in Gb = Ks+Vs region ----
    float* Gb = Ks;   // 128 x 128 floats spanning dead Ks+Vs (contiguous)
    {   // pass 1: gate rows -> silu into Gb
        ull acc[8][4] = {};
        gemm_core<8, 4, PXF, 16>(ffn_in_w + 128 * 128, Hs, Wts, acc, tid);
        #pragma unroll
        for (int i = 0; i < 8; ++i) {
            int r = ty + 16 * i;
            float bg = ffn_in_b[r + 128];
            #pragma unroll
            for (int jp = 0; jp < 4; ++jp) {
                float g0, g1; unpack2(acc[i][jp], g0, g1);
                int fl = 2 * (tx + 16 * jp);
                Gb[r * PXF + fl]     = silu_f(g0 + bg);
                Gb[r * PXF + fl + 1] = silu_f(g1 + bg);
            }
        }
    }
    {   // pass 2: a rows; m2 = (a+b)*silu(g) into Gb (same-thread same-slot)
        ull acc[8][4] = {};
        gemm_core<8, 4, PXF, 16>(ffn_in_w, Hs, Wts, acc, tid);
        #pragma unroll
        for (int i = 0; i < 8; ++i) {
            int r = ty + 16 * i;
            float ba = ffn_in_b[r];
            #pragma unroll
            for (int jp = 0; jp < 4; ++jp) {
                float a0, a1; unpack2(acc[i][jp], a0, a1);
                int fl = 2 * (tx + 16 * jp);
                Gb[r * PXF + fl]     = (a0 + ba) * Gb[r * PXF + fl];
                Gb[r * PXF + fl + 1] = (a1 + ba) * Gb[r * PXF + fl + 1];
            }
        }
    }
    // ---- GEMM6: out = ffn_out @ m2 + ffn_out_b + hidden -> global ----
    {
        ull acc[8][4] = {};
        gemm_core<8, 4, PXF, 16>(ffn_out_w, Gb, Wts, acc, tid);
        float* obase = out + ((size_t)b * C * T + t) * F + f0;
        #pragma unroll
        for (int i = 0; i < 8; ++i) {
            int r = ty + 16 * i;
            float bias = ffn_out_b[r];
            #pragma unroll
            for (int jp = 0; jp < 4; ++jp) {
                float lo, hi; unpack2(acc[i][jp], lo, hi);
                int fl = 2 * (tx + 16 * jp);
                lo += bias + Xs[r * PXF + fl];
                hi += bias + Xs[r * PXF + fl + 1];
                *reinterpret_cast<float2*>(obase + (size_t)r * (T * F) + fl) = make_float2(lo, hi);
            }
        }
    }
}

// ---------------------------------------------------------------------------
extern "C" void kernel_launch(void* const* d_in, const int* in_sizes, int n_in,
                              void* d_out, int out_size)
{
    const float* latent      = (const float*)d_in[0];
    const float* side        = (const float*)d_in[1];
    const float* basis       = (const float*)d_in[2];
    const float* lp_gamma    = (const float*)d_in[3];
    const float* lp_w        = (const float*)d_in[4];
    const float* lp_b        = (const float*)d_in[5];
    const float* qn_gamma    = (const float*)d_in[6];
    const float* qmlp_in_w   = (const float*)d_in[7];
    const float* qmlp_in_b   = (const float*)d_in[8];
    const float* qmlp_out_w  = (const float*)d_in[9];
    const float* qmlp_out_b  = (const float*)d_in[10];
    const float* q_w         = (const float*)d_in[11];
    const float* q_b         = (const float*)d_in[12];
    const float* k_w         = (const float*)d_in[13];
    const float* k_b         = (const float*)d_in[14];
    const float* v_w         = (const float*)d_in[15];
    const float* v_b         = (const float*)d_in[16];
    const float* o_w         = (const float*)d_in[17];
    const float* o_b         = (const float*)d_in[18];
    const float* ffn_gamma   = (const float*)d_in[19];
    const float* ffn_in_w    = (const float*)d_in[20];
    const float* ffn_in_b    = (const float*)d_in[21];
    const float* ffn_out_w   = (const float*)d_in[22];
    const float* ffn_out_b   = (const float*)d_in[23];
    const float* score_scale = (const float*)d_in[24];
    const float* prior_scale = (const float*)d_in[25];
    const float* qss         = (const float*)d_in[26];
    float* out = (float*)d_out;

    cudaFuncSetAttribute(latent_kernel, cudaFuncAttributeMaxDynamicSharedMemorySize, K1_SMEM_BYTES);
    cudaFuncSetAttribute(main_kernel,   cudaFuncAttributeMaxDynamicSharedMemorySize, K2_SMEM_BYTES);

    latent_kernel<<<B * T, 256, K1_SMEM_BYTES>>>(
        latent, lp_gamma, lp_w, lp_b, k_w, k_b, v_w, v_b);

    main_kernel<<<dim3(F / FC, T, B), 256, K2_SMEM_BYTES>>>(
        side, basis, qn_gamma,
        qmlp_in_w, qmlp_in_b, qmlp_out_w, qmlp_out_b,
        q_w, q_b, o_w, o_b,
        ffn_gamma, ffn_in_w, ffn_in_b, ffn_out_w, ffn_out_b,
        score_scale, prior_scale, qss, out);
}